// round 1
// baseline (speedup 1.0000x reference)
#include <cuda_runtime.h>

#define BB 2
#define DM 192
#define DI 384
#define DS 16
#define DR 12
#define HH 64
#define WW 64
#define LL 4096
#define NROWS (BB*LL)   // 8192

// ---------------- scratch (static device globals; no allocation) ----------------
__device__ float g_xa_pre[BB*DI*LL];   // xz first half, NCHW for conv
__device__ float g_c_pre [BB*DI*LL];   // condition proj, NCHW
__device__ float g_xa_conv[BB*DI*LL];  // silu(dwconv(xa))
__device__ float g_c_conv [BB*DI*LL];  // silu(dwconv(c))
__device__ float g_z     [NROWS*DI];   // silu(z), (b*l, d)
__device__ float g_u     [BB*DI*LL];   // xs (scan-ordered u)
__device__ float g_delta [BB*DI*LL];   // softplus(dt), scan-ordered
__device__ float g_Bsc   [BB*DS*LL];
__device__ float g_Csc   [BB*DS*LL];
__device__ float g_y     [NROWS*DI];   // scan output, spatial order, (b*l, d)
__device__ float g_yz    [NROWS*DI];   // layernorm*z, GEMM-out input

__device__ __forceinline__ float silu_f(float v){ return v / (1.f + __expf(-v)); }

// ---------------- generic tiled GEMM: C[M,N] = A[M,K] * B[N,K]^T ----------------
// mode 0: xz epilogue (split xa->NCHW, silu(z)->NLC)
// mode 1: cond epilogue (->NCHW)
// mode 2: plain store to `out` (A is g_yz)
__global__ void gemm_kernel(const float* __restrict__ A, const float* __restrict__ Bw,
                            int M, int N, int K, int mode, float* __restrict__ out)
{
    __shared__ float As[16][64];
    __shared__ float Bs[16][64];
    int tid = threadIdx.x;
    int tx = tid & 15, ty = tid >> 4;
    int n0 = blockIdx.x * 64;
    int m0 = blockIdx.y * 64;
    const float* Ap = (mode == 2) ? g_yz : A;

    float acc[4][4];
    #pragma unroll
    for (int i = 0; i < 4; i++)
        #pragma unroll
        for (int j = 0; j < 4; j++) acc[i][j] = 0.f;

    int lr = tid >> 2;          // 0..63
    int lc = (tid & 3) * 4;     // 0,4,8,12

    for (int k0 = 0; k0 < K; k0 += 16) {
        float4 av = *(const float4*)(Ap + (size_t)(m0 + lr) * K + k0 + lc);
        float4 bv = *(const float4*)(Bw + (size_t)(n0 + lr) * K + k0 + lc);
        As[lc+0][lr] = av.x; As[lc+1][lr] = av.y; As[lc+2][lr] = av.z; As[lc+3][lr] = av.w;
        Bs[lc+0][lr] = bv.x; Bs[lc+1][lr] = bv.y; Bs[lc+2][lr] = bv.z; Bs[lc+3][lr] = bv.w;
        __syncthreads();
        #pragma unroll
        for (int k = 0; k < 16; k++) {
            float4 a = *(const float4*)(&As[k][ty*4]);
            float4 b = *(const float4*)(&Bs[k][tx*4]);
            float ar[4] = {a.x, a.y, a.z, a.w};
            float br[4] = {b.x, b.y, b.z, b.w};
            #pragma unroll
            for (int i = 0; i < 4; i++)
                #pragma unroll
                for (int j = 0; j < 4; j++)
                    acc[i][j] = fmaf(ar[i], br[j], acc[i][j]);
        }
        __syncthreads();
    }

    #pragma unroll
    for (int i = 0; i < 4; i++) {
        int m = m0 + ty*4 + i;
        int b = m / LL, l = m % LL;
        #pragma unroll
        for (int j = 0; j < 4; j++) {
            int n = n0 + tx*4 + j;
            float v = acc[i][j];
            if (mode == 0) {
                if (n < DI) g_xa_pre[((size_t)(b*DI + n))*LL + l] = v;
                else        g_z[(size_t)m*DI + (n - DI)] = silu_f(v);
            } else if (mode == 1) {
                g_c_pre[((size_t)(b*DI + n))*LL + l] = v;
            } else {
                out[(size_t)m*N + n] = v;
            }
        }
    }
}

// ---------------- depthwise conv 3x3 SAME + bias + silu (both tensors) ----------------
__global__ void dwconv_silu_kernel(const float* __restrict__ conv_w, const float* __restrict__ conv_b,
                                   const float* __restrict__ con_w,  const float* __restrict__ con_b)
{
    int idx = blockIdx.x * blockDim.x + threadIdx.x;
    int per = BB * DI * LL;
    int t = idx / per;        // 0 = xa, 1 = cond
    int r = idx % per;
    int bd = r / LL;
    int l  = r % LL;
    int d  = bd % DI;
    int y = l >> 6, x = l & 63;
    const float* in   = t ? g_c_pre : g_xa_pre;
    const float* wp   = (t ? con_w : conv_w) + d * 9;
    float acc = (t ? con_b : conv_b)[d];
    const float* base = in + (size_t)bd * LL;
    #pragma unroll
    for (int ky = -1; ky <= 1; ky++) {
        int yy = y + ky;
        if (yy < 0 || yy >= HH) continue;
        #pragma unroll
        for (int kx = -1; kx <= 1; kx++) {
            int xx = x + kx;
            if (xx < 0 || xx >= WW) continue;
            acc = fmaf(base[yy * WW + xx], wp[(ky+1)*3 + (kx+1)], acc);
        }
    }
    (t ? g_c_conv : g_xa_conv)[(size_t)bd * LL + l] = silu_f(acc);
}

// ---------------- per-(b,l): gather + x_proj(44) + dt_proj + softplus ----------------
__global__ void proj_kernel(const float* __restrict__ x_proj_w, const float* __restrict__ dt_proj_w,
                            const float* __restrict__ dt_proj_b, const int* __restrict__ scan_path)
{
    int j = blockIdx.x & (LL - 1);
    int b = blockIdx.x >> 12;        // / LL
    __shared__ float s[DI];
    __shared__ float xd[DR + 2*DS];  // 44
    int lp = scan_path[j];

    for (int d = threadIdx.x; d < DI; d += 128) {
        float xv = g_xa_conv[((size_t)(b*DI + d))*LL + lp];
        float cv = g_c_conv [((size_t)(b*DI + d))*LL + lp];
        s[d] = xv + cv;
        g_u[((size_t)(b*DI + d))*LL + j] = xv;   // u = xs (xa only)
    }
    __syncthreads();

    int w = threadIdx.x >> 5, lane = threadIdx.x & 31;
    for (int c = w; c < DR + 2*DS; c += 4) {
        float acc = 0.f;
        const float* wrow = x_proj_w + (size_t)c * DI;
        for (int d = lane; d < DI; d += 32) acc = fmaf(wrow[d], s[d], acc);
        #pragma unroll
        for (int o = 16; o > 0; o >>= 1) acc += __shfl_xor_sync(0xFFFFFFFFu, acc, o);
        if (lane == 0) xd[c] = acc;
    }
    __syncthreads();

    for (int d = threadIdx.x; d < DI; d += 128) {
        float acc = dt_proj_b[d];
        const float* wrow = dt_proj_w + (size_t)d * DR;
        #pragma unroll
        for (int r = 0; r < DR; r++) acc = fmaf(wrow[r], xd[r], acc);
        float delta = (acc > 20.f) ? acc : log1pf(expf(acc));   // softplus
        g_delta[((size_t)(b*DI + d))*LL + j] = delta;
    }
    if (threadIdx.x < DS) {
        g_Bsc[((size_t)(b*DS + threadIdx.x))*LL + j] = xd[DR + threadIdx.x];
        g_Csc[((size_t)(b*DS + threadIdx.x))*LL + j] = xd[DR + DS + threadIdx.x];
    }
}

// ---------------- selective scan: 16 lanes per (b,d) channel ----------------
__global__ void scan_kernel(const float* __restrict__ A_logs, const float* __restrict__ Ds,
                            const int* __restrict__ scan_path)
{
    int grp  = threadIdx.x >> 4;           // 0..7
    int lane = threadIdx.x & 15;           // state index n
    int gid  = blockIdx.x * 8 + grp;       // 0..767
    int b = gid / DI, d = gid % DI;

    float a_coef = -expf(A_logs[d * DS + lane]);
    float Dd = Ds[d];
    const float* dptr = g_delta + ((size_t)(b*DI + d))*LL;
    const float* uptr = g_u     + ((size_t)(b*DI + d))*LL;
    const float* bptr = g_Bsc   + ((size_t)(b*DS + lane))*LL;
    const float* cptr = g_Csc   + ((size_t)(b*DS + lane))*LL;

    float h = 0.f;
    float delta = dptr[0], u = uptr[0], Bv = bptr[0], Cv = cptr[0];

    for (int l = 0; l < LL; l++) {
        float nd = 0.f, nu = 0.f, nB = 0.f, nC = 0.f;
        if (l + 1 < LL) { nd = dptr[l+1]; nu = uptr[l+1]; nB = bptr[l+1]; nC = cptr[l+1]; }
        float dA = __expf(delta * a_coef);
        h = fmaf(dA, h, delta * Bv * u);
        float p = h * Cv;
        p += __shfl_xor_sync(0xFFFFFFFFu, p, 1);
        p += __shfl_xor_sync(0xFFFFFFFFu, p, 2);
        p += __shfl_xor_sync(0xFFFFFFFFu, p, 4);
        p += __shfl_xor_sync(0xFFFFFFFFu, p, 8);
        if (lane == 0) {
            int pos = __ldg(&scan_path[l]);   // scatter: scan order -> spatial order
            g_y[((size_t)(b*LL + pos))*DI + d] = fmaf(u, Dd, p);
        }
        delta = nd; u = nu; Bv = nB; Cv = nC;
    }
}

// ---------------- layernorm over d + multiply by silu(z) ----------------
__global__ void ln_mul_kernel(const float* __restrict__ ln_w, const float* __restrict__ ln_b)
{
    int row = blockIdx.x;      // b*LL + l
    const float* yr = g_y + (size_t)row * DI;
    float v0 = yr[threadIdx.x], v1 = yr[threadIdx.x + 128], v2 = yr[threadIdx.x + 256];
    float s = v0 + v1 + v2;
    float q = v0*v0 + v1*v1 + v2*v2;
    #pragma unroll
    for (int o = 16; o > 0; o >>= 1) {
        s += __shfl_xor_sync(0xFFFFFFFFu, s, o);
        q += __shfl_xor_sync(0xFFFFFFFFu, q, o);
    }
    __shared__ float ss[4], sq[4];
    int w = threadIdx.x >> 5, lane = threadIdx.x & 31;
    if (lane == 0) { ss[w] = s; sq[w] = q; }
    __syncthreads();
    s = ss[0] + ss[1] + ss[2] + ss[3];
    q = sq[0] + sq[1] + sq[2] + sq[3];
    float mean = s * (1.f / DI);
    float var  = q * (1.f / DI) - mean * mean;
    float rstd = rsqrtf(var + 1e-5f);
    const float* zr = g_z + (size_t)row * DI;
    float* o = g_yz + (size_t)row * DI;
    float vv[3] = {v0, v1, v2};
    #pragma unroll
    for (int i = 0; i < 3; i++) {
        int d = threadIdx.x + i * 128;
        o[d] = ((vv[i] - mean) * rstd * ln_w[d] + ln_b[d]) * zr[d];
    }
}

// ---------------- launch ----------------
extern "C" void kernel_launch(void* const* d_in, const int* in_sizes, int n_in,
                              void* d_out, int out_size)
{
    const float* x          = (const float*)d_in[0];
    const float* cond       = (const float*)d_in[1];
    const float* W_in       = (const float*)d_in[2];
    const float* W_con      = (const float*)d_in[3];
    const float* conv_w     = (const float*)d_in[4];
    const float* conv_b     = (const float*)d_in[5];
    const float* con_conv_w = (const float*)d_in[6];
    const float* con_conv_b = (const float*)d_in[7];
    const float* x_proj_w   = (const float*)d_in[8];
    const float* dt_proj_w  = (const float*)d_in[9];
    const float* dt_proj_b  = (const float*)d_in[10];
    const float* A_logs     = (const float*)d_in[11];
    const float* Ds         = (const float*)d_in[12];
    const float* ln_w       = (const float*)d_in[13];
    const float* ln_b       = (const float*)d_in[14];
    const float* W_out      = (const float*)d_in[15];
    const int*   scan_path  = (const int*)d_in[16];
    float* out = (float*)d_out;

    dim3 g1(2*DI/64, NROWS/64);
    gemm_kernel<<<g1, 256>>>(x, W_in, NROWS, 2*DI, DM, 0, nullptr);
    dim3 g2(DI/64, NROWS/64);
    gemm_kernel<<<g2, 256>>>(cond, W_con, NROWS, DI, DM, 1, nullptr);
    dwconv_silu_kernel<<<(2*BB*DI*LL)/256, 256>>>(conv_w, conv_b, con_conv_w, con_conv_b);
    proj_kernel<<<NROWS, 128>>>(x_proj_w, dt_proj_w, dt_proj_b, scan_path);
    scan_kernel<<<(BB*DI)/8, 128>>>(A_logs, Ds, scan_path);
    ln_mul_kernel<<<NROWS, 128>>>(ln_w, ln_b);
    dim3 g3(DM/64, NROWS/64);
    gemm_kernel<<<g3, 256>>>(nullptr, W_out, NROWS, DM, DI, 2, out);
}

// round 3
// speedup vs baseline: 1.8676x; 1.8676x over previous
#include <cuda_runtime.h>

#define BB 2
#define DM 192
#define DI 384
#define DS 16
#define DR 12
#define HH 64
#define WW 64
#define LL 4096
#define NROWS (BB*LL)   // 8192

// ---------------- scratch ----------------
__device__ float  g_xa_pre[BB*DI*LL];   // xz first half, NCHW
__device__ float  g_c_pre [BB*DI*LL];
__device__ float  g_xa_conv[BB*DI*LL];  // silu(dwconv(xa))
__device__ float  g_c_conv [BB*DI*LL];
__device__ float  g_z     [NROWS*DI];   // silu(z), (b*l, d)
__device__ float2 g_du    [BB*LL*DI];   // (delta, u) in scan order [b][j][d]
__device__ float2 g_bc    [BB*LL*DS];   // (B_n, C_n) in scan order [b][j][n]
__device__ float  g_y     [NROWS*DI];   // scan output, spatial order, (b*l, d)
__device__ float  g_yz    [NROWS*DI];

__device__ __forceinline__ float silu_f(float v){ return v / (1.f + __expf(-v)); }

__device__ __forceinline__ void cpa8(unsigned dst, const void* src){
    asm volatile("cp.async.ca.shared.global [%0], [%1], 8;\n" :: "r"(dst), "l"(src));
}
__device__ __forceinline__ void cpa16(unsigned dst, const void* src){
    asm volatile("cp.async.ca.shared.global [%0], [%1], 16;\n" :: "r"(dst), "l"(src));
}
__device__ __forceinline__ void cp_commit(){ asm volatile("cp.async.commit_group;\n"); }
__device__ __forceinline__ void cp_wait1(){ asm volatile("cp.async.wait_group 1;\n"); }
__device__ __forceinline__ void cp_wait0(){ asm volatile("cp.async.wait_group 0;\n"); }

// =======================================================================
// GEMM: C[M,N] = A[M,K] * B[N,K]^T.  128x64 tile, 256 thr, 8x4 micro.
// MODE 0: xz (n<DI -> xa NCHW via transpose; n>=DI -> silu(z) row-major)
// MODE 1: cond -> NCHW via transpose
// MODE 2: plain store to out
// =======================================================================
#define AS_STRIDE 132   // % 4 == 0 (16B-aligned float4 rows)
#define BS_STRIDE 68    // % 4 == 0 (16B-aligned float4 rows)

template<int MODE>
__global__ void __launch_bounds__(256) gemm_k(const float* __restrict__ A,
        const float* __restrict__ Bw, int M, int N, int K, float* __restrict__ out)
{
    __shared__ __align__(16) union {
        struct { float As[2][16*AS_STRIDE]; float Bs[2][16*BS_STRIDE]; } s;
        float Ts[64*129];
    } u;

    int tid = threadIdx.x;
    int tx = tid & 15, ty = tid >> 4;
    int n0 = blockIdx.x * 64;
    int m0 = blockIdx.y * 128;
    const float* Ap = (MODE == 2) ? g_yz : A;

    int am  = tid >> 1;          // 0..127
    int akq = (tid & 1) * 8;     // 0 or 8
    int bn  = tid >> 2;          // 0..63
    int bkq = (tid & 3) * 4;     // 0,4,8,12
    const float* aP = Ap + (size_t)(m0 + am) * K + akq;
    const float* bP = Bw + (size_t)(n0 + bn) * K + bkq;

    float acc[8][4];
    #pragma unroll
    for (int i = 0; i < 8; i++)
        #pragma unroll
        for (int j = 0; j < 4; j++) acc[i][j] = 0.f;

    float4 ar0 = *(const float4*)(aP);
    float4 ar1 = *(const float4*)(aP + 4);
    float4 br0 = *(const float4*)(bP);

    int buf = 0;
    {
        float* As = u.s.As[0]; float* Bs = u.s.Bs[0];
        As[(akq+0)*AS_STRIDE+am]=ar0.x; As[(akq+1)*AS_STRIDE+am]=ar0.y;
        As[(akq+2)*AS_STRIDE+am]=ar0.z; As[(akq+3)*AS_STRIDE+am]=ar0.w;
        As[(akq+4)*AS_STRIDE+am]=ar1.x; As[(akq+5)*AS_STRIDE+am]=ar1.y;
        As[(akq+6)*AS_STRIDE+am]=ar1.z; As[(akq+7)*AS_STRIDE+am]=ar1.w;
        Bs[(bkq+0)*BS_STRIDE+bn]=br0.x; Bs[(bkq+1)*BS_STRIDE+bn]=br0.y;
        Bs[(bkq+2)*BS_STRIDE+bn]=br0.z; Bs[(bkq+3)*BS_STRIDE+bn]=br0.w;
    }
    __syncthreads();

    int nch = K / 16;
    for (int c = 0; c < nch; c++) {
        if (c + 1 < nch) {
            ar0 = *(const float4*)(aP + (c+1)*16);
            ar1 = *(const float4*)(aP + (c+1)*16 + 4);
            br0 = *(const float4*)(bP + (c+1)*16);
        }
        const float* As = u.s.As[buf];
        const float* Bs = u.s.Bs[buf];
        #pragma unroll
        for (int kk = 0; kk < 16; kk++) {
            float4 a0 = *(const float4*)&As[kk*AS_STRIDE + ty*8];
            float4 a1 = *(const float4*)&As[kk*AS_STRIDE + ty*8 + 4];
            float4 b0 = *(const float4*)&Bs[kk*BS_STRIDE + tx*4];
            float ar[8] = {a0.x,a0.y,a0.z,a0.w,a1.x,a1.y,a1.z,a1.w};
            float br[4] = {b0.x,b0.y,b0.z,b0.w};
            #pragma unroll
            for (int i = 0; i < 8; i++)
                #pragma unroll
                for (int j = 0; j < 4; j++)
                    acc[i][j] = fmaf(ar[i], br[j], acc[i][j]);
        }
        if (c + 1 < nch) {
            __syncthreads();
            float* Asw = u.s.As[buf^1]; float* Bsw = u.s.Bs[buf^1];
            Asw[(akq+0)*AS_STRIDE+am]=ar0.x; Asw[(akq+1)*AS_STRIDE+am]=ar0.y;
            Asw[(akq+2)*AS_STRIDE+am]=ar0.z; Asw[(akq+3)*AS_STRIDE+am]=ar0.w;
            Asw[(akq+4)*AS_STRIDE+am]=ar1.x; Asw[(akq+5)*AS_STRIDE+am]=ar1.y;
            Asw[(akq+6)*AS_STRIDE+am]=ar1.z; Asw[(akq+7)*AS_STRIDE+am]=ar1.w;
            Bsw[(bkq+0)*BS_STRIDE+bn]=br0.x; Bsw[(bkq+1)*BS_STRIDE+bn]=br0.y;
            Bsw[(bkq+2)*BS_STRIDE+bn]=br0.z; Bsw[(bkq+3)*BS_STRIDE+bn]=br0.w;
            __syncthreads();
            buf ^= 1;
        }
    }

    bool transp = (MODE == 0 && n0 < DI) || (MODE == 1);
    if (transp) {
        __syncthreads();
        #pragma unroll
        for (int i = 0; i < 8; i++)
            #pragma unroll
            for (int j = 0; j < 4; j++)
                u.Ts[(tx*4+j)*129 + ty*8+i] = acc[i][j];
        __syncthreads();
        int b = m0 >> 12, l0 = m0 & 4095;
        float* dst = (MODE == 0) ? g_xa_pre : g_c_pre;
        for (int e = tid; e < 64*128; e += 256) {
            int row = e >> 7, cc = e & 127;
            dst[((size_t)(b*DI + n0 + row))*LL + l0 + cc] = u.Ts[row*129 + cc];
        }
    } else {
        #pragma unroll
        for (int i = 0; i < 8; i++) {
            int m = m0 + ty*8 + i;
            #pragma unroll
            for (int j = 0; j < 4; j++) {
                int n = n0 + tx*4 + j;
                float v = acc[i][j];
                if (MODE == 0)      g_z[(size_t)m*DI + (n - DI)] = silu_f(v);
                else if (MODE == 2) out[(size_t)m*N + n] = v;
            }
        }
    }
}

// =======================================================================
// depthwise conv 3x3 SAME + bias + silu, one (tensor,b,d) image per block
// =======================================================================
__global__ void __launch_bounds__(256) dwconv_k(const float* __restrict__ conv_w,
        const float* __restrict__ conv_b, const float* __restrict__ con_w,
        const float* __restrict__ con_b)
{
    __shared__ __align__(16) float img[LL];
    int blk = blockIdx.x;
    int t  = blk >= BB*DI;
    int bd = t ? blk - BB*DI : blk;
    int d  = bd % DI;
    const float* in  = (t ? g_c_pre : g_xa_pre) + (size_t)bd * LL;
    float*       oup = (t ? g_c_conv : g_xa_conv) + (size_t)bd * LL;
    const float* wp  = (t ? con_w : conv_w) + d * 9;
    float bias = (t ? con_b : conv_b)[d];

    #pragma unroll
    for (int i = 0; i < 4; i++)
        *(float4*)&img[(threadIdx.x + 256*i)*4] = *(const float4*)&in[(threadIdx.x + 256*i)*4];
    float w0=wp[0],w1=wp[1],w2=wp[2],w3=wp[3],w4=wp[4],w5=wp[5],w6=wp[6],w7=wp[7],w8=wp[8];
    __syncthreads();

    #pragma unroll
    for (int i = 0; i < 16; i++) {
        int l = threadIdx.x + 256*i;
        int y = l >> 6, x = l & 63;
        float acc = bias;
        bool yl = y > 0, yh = y < 63, xl = x > 0, xh = x < 63;
        if (yl) {
            if (xl) acc = fmaf(img[l-65], w0, acc);
            acc = fmaf(img[l-64], w1, acc);
            if (xh) acc = fmaf(img[l-63], w2, acc);
        }
        if (xl) acc = fmaf(img[l-1], w3, acc);
        acc = fmaf(img[l], w4, acc);
        if (xh) acc = fmaf(img[l+1], w5, acc);
        if (yh) {
            if (xl) acc = fmaf(img[l+63], w6, acc);
            acc = fmaf(img[l+64], w7, acc);
            if (xh) acc = fmaf(img[l+65], w8, acc);
        }
        oup[l] = silu_f(acc);
    }
}

// =======================================================================
// proj: per 8-pixel tile (spatial order), compute x_proj + dt_proj +
// softplus; scatter (delta,u) and (B,C) into scan-order layouts.
// =======================================================================
#define PIX 8
#define SST 9   // smem stride

__global__ void __launch_bounds__(256) proj_k(const float* __restrict__ x_proj_w,
        const float* __restrict__ dt_proj_w, const float* __restrict__ dt_proj_b,
        const int* __restrict__ rev_scan)
{
    __shared__ float s_s [DI*SST];
    __shared__ float xa_s[DI*SST];
    __shared__ float xd_s[PIX][48];

    int tid = threadIdx.x;
    int blk = blockIdx.x;
    int b   = blk >> 9;            // 512 blocks per batch
    int l0  = (blk & 511) * PIX;

    // load phase: coalesced along l
    {
        int px = tid & 7, drow = tid >> 3;   // 32 d rows per pass
        #pragma unroll
        for (int i = 0; i < 12; i++) {
            int d = drow + 32*i;
            float xv = g_xa_conv[((size_t)(b*DI + d))*LL + l0 + px];
            float cv = g_c_conv [((size_t)(b*DI + d))*LL + l0 + px];
            xa_s[d*SST + px] = xv;
            s_s [d*SST + px] = xv + cv;
        }
    }
    __syncthreads();

    // x_proj: 44 outputs per pixel
    {
        int px = tid & 7, c = tid >> 3;      // c 0..31
        #pragma unroll
        for (int pass = 0; pass < 2; pass++) {
            int cc = c + 32*pass;
            if (cc < DR + 2*DS) {
                const float* wrow = x_proj_w + (size_t)cc * DI;
                float acc = 0.f;
                #pragma unroll 4
                for (int d = 0; d < DI; d++)
                    acc = fmaf(__ldg(&wrow[d]), s_s[d*SST + px], acc);
                xd_s[px][cc] = acc;
            }
        }
    }
    __syncthreads();

    // delta/u/B/C phase: one warp per pixel
    {
        int w = tid >> 5, lane = tid & 31;
        int px = w;
        int j  = __ldg(&rev_scan[l0 + px]);
        if (lane < DS) {
            g_bc[((size_t)b*LL + j)*DS + lane] =
                make_float2(xd_s[px][DR + lane], xd_s[px][DR + DS + lane]);
        }
        #pragma unroll
        for (int i = 0; i < 12; i++) {
            int d = lane + 32*i;
            const float* wrow = dt_proj_w + (size_t)d * DR;
            float acc = dt_proj_b[d];
            #pragma unroll
            for (int r = 0; r < DR; r++) acc = fmaf(wrow[r], xd_s[px][r], acc);
            float delta = (acc > 20.f) ? acc : log1pf(__expf(acc));
            g_du[((size_t)b*LL + j)*DI + d] = make_float2(delta, xa_s[d*SST + px]);
        }
    }
}

// =======================================================================
// selective scan: block = 8 channels of one batch, 128 thr
// 32-step tiles staged via cp.async; reduction over states via smem pass.
// =======================================================================
#define TSTEP 32
#define NTILE (LL/TSTEP)   // 128

__global__ void __launch_bounds__(128) scan_k(const float* __restrict__ A_logs,
        const float* __restrict__ Ds, const int* __restrict__ scan_path)
{
    __shared__ __align__(16) float2 du2[2][TSTEP][8];
    __shared__ __align__(16) float2 bc2[2][TSTEP][DS];
    __shared__ float  ps[TSTEP*8*17];
    __shared__ float  s_D[8];

    int tid = threadIdx.x;
    int b   = blockIdx.x / 48;
    int d0  = (blockIdx.x % 48) * 8;
    int wid = tid >> 5, lane = tid & 31;
    int g = lane >> 4, n = lane & 15;
    int ch = wid*2 + g;
    int d = d0 + ch;

    float a_coef = -__expf(A_logs[d*DS + n]);
    if (tid < 8) s_D[tid] = Ds[d0 + tid];

    unsigned du_sm = (unsigned)__cvta_generic_to_shared(&du2[0][0][0]);
    unsigned bc_sm = (unsigned)__cvta_generic_to_shared(&bc2[0][0][0]);
    const float2* du_g = g_du + (size_t)b*LL*DI + d0;
    const float2* bc_g = g_bc + (size_t)b*LL*DS;

    // stage tile 0 into buf 0
    {
        #pragma unroll
        for (int i = 0; i < 2; i++) {
            int e = tid + 128*i;
            int jj = e >> 3, c = e & 7;
            cpa8(du_sm + (unsigned)((jj*8 + c)*8), du_g + (size_t)jj*DI + c);
        }
        #pragma unroll
        for (int i = 0; i < 2; i++) {
            int e = tid + 128*i;
            int jj = e >> 3, q = e & 7;
            cpa16(bc_sm + (unsigned)((jj*DS + q*2)*8), bc_g + (size_t)jj*DS + q*2);
        }
        cp_commit();
    }

    float h = 0.f;
    int buf = 0;
    for (int T = 0; T < NTILE; T++) {
        if (T + 1 < NTILE) {
            int o = (buf^1) * TSTEP;
            #pragma unroll
            for (int i = 0; i < 2; i++) {
                int e = tid + 128*i;
                int jj = e >> 3, c = e & 7;
                cpa8(du_sm + (unsigned)(((o+jj)*8 + c)*8),
                     du_g + (size_t)((T+1)*TSTEP + jj)*DI + c);
            }
            #pragma unroll
            for (int i = 0; i < 2; i++) {
                int e = tid + 128*i;
                int jj = e >> 3, q = e & 7;
                cpa16(bc_sm + (unsigned)(((o+jj)*DS + q*2)*8),
                      bc_g + (size_t)((T+1)*TSTEP + jj)*DS + q*2);
            }
            cp_commit();
            cp_wait1();
        } else {
            cp_wait0();
        }
        __syncthreads();

        // compute 32 steps
        #pragma unroll 8
        for (int jj = 0; jj < TSTEP; jj++) {
            float2 du = du2[buf][jj][ch];
            float2 bc = bc2[buf][jj][n];
            float dA = __expf(du.x * a_coef);
            h = fmaf(dA, h, du.x * du.y * bc.x);
            ps[(jj*8 + ch)*17 + n] = h * bc.y;
        }
        __syncthreads();

        // reduce 16 states per (jj,ch) and scatter-store
        #pragma unroll
        for (int i = 0; i < 2; i++) {
            int e = tid + 128*i;
            int jj = e >> 3, c = e & 7;
            const float* p = &ps[(jj*8 + c)*17];
            float sum = p[0];
            #pragma unroll
            for (int k = 1; k < DS; k++) sum += p[k];
            float uval = du2[buf][jj][c].y;
            int pos = __ldg(&scan_path[T*TSTEP + jj]);
            g_y[((size_t)b*LL + pos)*DI + d0 + c] = fmaf(uval, s_D[c], sum);
        }
        buf ^= 1;
    }
}

// =======================================================================
// layernorm over d + multiply by silu(z)
// =======================================================================
__global__ void __launch_bounds__(128) ln_mul_k(const float* __restrict__ ln_w,
                                                const float* __restrict__ ln_b)
{
    int row = blockIdx.x;
    const float* yr = g_y + (size_t)row * DI;
    float v0 = yr[threadIdx.x], v1 = yr[threadIdx.x + 128], v2 = yr[threadIdx.x + 256];
    float s = v0 + v1 + v2;
    float q = v0*v0 + v1*v1 + v2*v2;
    #pragma unroll
    for (int o = 16; o > 0; o >>= 1) {
        s += __shfl_xor_sync(0xFFFFFFFFu, s, o);
        q += __shfl_xor_sync(0xFFFFFFFFu, q, o);
    }
    __shared__ float ss[4], sq[4];
    int w = threadIdx.x >> 5, lane = threadIdx.x & 31;
    if (lane == 0) { ss[w] = s; sq[w] = q; }
    __syncthreads();
    s = ss[0] + ss[1] + ss[2] + ss[3];
    q = sq[0] + sq[1] + sq[2] + sq[3];
    float mean = s * (1.f / DI);
    float var  = q * (1.f / DI) - mean * mean;
    float rstd = rsqrtf(var + 1e-5f);
    const float* zr = g_z + (size_t)row * DI;
    float* o = g_yz + (size_t)row * DI;
    float vv[3] = {v0, v1, v2};
    #pragma unroll
    for (int i = 0; i < 3; i++) {
        int dd = threadIdx.x + i * 128;
        o[dd] = ((vv[i] - mean) * rstd * ln_w[dd] + ln_b[dd]) * zr[dd];
    }
}

// ---------------- launch ----------------
extern "C" void kernel_launch(void* const* d_in, const int* in_sizes, int n_in,
                              void* d_out, int out_size)
{
    const float* x          = (const float*)d_in[0];
    const float* cond       = (const float*)d_in[1];
    const float* W_in       = (const float*)d_in[2];
    const float* W_con      = (const float*)d_in[3];
    const float* conv_w     = (const float*)d_in[4];
    const float* conv_b     = (const float*)d_in[5];
    const float* con_conv_w = (const float*)d_in[6];
    const float* con_conv_b = (const float*)d_in[7];
    const float* x_proj_w   = (const float*)d_in[8];
    const float* dt_proj_w  = (const float*)d_in[9];
    const float* dt_proj_b  = (const float*)d_in[10];
    const float* A_logs     = (const float*)d_in[11];
    const float* Ds         = (const float*)d_in[12];
    const float* ln_w       = (const float*)d_in[13];
    const float* ln_b       = (const float*)d_in[14];
    const float* W_out      = (const float*)d_in[15];
    const int*   scan_path  = (const int*)d_in[16];
    const int*   rev_scan   = (const int*)d_in[17];
    float* out = (float*)d_out;

    gemm_k<0><<<dim3(2*DI/64, NROWS/128), 256>>>(x,    W_in,  NROWS, 2*DI, DM, nullptr);
    gemm_k<1><<<dim3(DI/64,   NROWS/128), 256>>>(cond, W_con, NROWS, DI,   DM, nullptr);
    dwconv_k<<<2*BB*DI, 256>>>(conv_w, conv_b, con_conv_w, con_conv_b);
    proj_k<<<NROWS/PIX, 256>>>(x_proj_w, dt_proj_w, dt_proj_b, rev_scan);
    scan_k<<<(BB*DI)/8, 128>>>(A_logs, Ds, scan_path);
    ln_mul_k<<<NROWS, 128>>>(ln_w, ln_b);
    gemm_k<2><<<dim3(DM/64, NROWS/128), 256>>>(nullptr, W_out, NROWS, DM, DI, out);
}

// round 4
// speedup vs baseline: 2.0881x; 1.1181x over previous
#include <cuda_runtime.h>

#define BB 2
#define DM 192
#define DI 384
#define DS 16
#define DR 12
#define HH 64
#define WW 64
#define LL 4096
#define NROWS (BB*LL)   // 8192

// ---------------- scratch ----------------
__device__ float  g_xa_pre[BB*DI*LL];   // xz first half, NCHW
__device__ float  g_c_pre [BB*DI*LL];
__device__ float  g_xa_conv[BB*DI*LL];  // silu(dwconv(xa))
__device__ float  g_c_conv [BB*DI*LL];
__device__ float  g_z     [NROWS*DI];   // silu(z), (b*l, d)
__device__ float2 g_du    [BB*LL*DI];   // (delta, u) in scan order [b][j][d]
__device__ float2 g_bc    [BB*LL*DS];   // (B_n, C_n) in scan order [b][j][n]
__device__ float  g_y     [NROWS*DI];   // scan output, spatial order, (b*l, d)
__device__ float  g_yz    [NROWS*DI];

__device__ __forceinline__ float silu_f(float v){ return v / (1.f + __expf(-v)); }

__device__ __forceinline__ void cpa8(unsigned dst, const void* src){
    asm volatile("cp.async.ca.shared.global [%0], [%1], 8;\n" :: "r"(dst), "l"(src));
}
__device__ __forceinline__ void cpa16(unsigned dst, const void* src){
    asm volatile("cp.async.ca.shared.global [%0], [%1], 16;\n" :: "r"(dst), "l"(src));
}
__device__ __forceinline__ void cp_commit(){ asm volatile("cp.async.commit_group;\n"); }
__device__ __forceinline__ void cp_wait1(){ asm volatile("cp.async.wait_group 1;\n"); }
__device__ __forceinline__ void cp_wait0(){ asm volatile("cp.async.wait_group 0;\n"); }

// =======================================================================
// GEMM: C[M,N] = A[M,K] * B[N,K]^T.  128x64 tile, 256 thr, 8x4 micro.
// MODE 0: xz (n<DI -> xa NCHW via transpose; n>=DI -> silu(z) row-major)
// MODE 1: cond -> NCHW via transpose
// MODE 2: plain store to out
// =======================================================================
#define AS_STRIDE 132   // % 4 == 0 (16B-aligned float4 rows)
#define BS_STRIDE 68    // % 4 == 0 (16B-aligned float4 rows)

template<int MODE>
__global__ void __launch_bounds__(256) gemm_k(const float* __restrict__ A,
        const float* __restrict__ Bw, int M, int N, int K, float* __restrict__ out)
{
    __shared__ __align__(16) union {
        struct { float As[2][16*AS_STRIDE]; float Bs[2][16*BS_STRIDE]; } s;
        float Ts[64*129];
    } u;

    int tid = threadIdx.x;
    int tx = tid & 15, ty = tid >> 4;
    int n0 = blockIdx.x * 64;
    int m0 = blockIdx.y * 128;
    const float* Ap = (MODE == 2) ? g_yz : A;

    int am  = tid >> 1;          // 0..127
    int akq = (tid & 1) * 8;     // 0 or 8
    int bn  = tid >> 2;          // 0..63
    int bkq = (tid & 3) * 4;     // 0,4,8,12
    const float* aP = Ap + (size_t)(m0 + am) * K + akq;
    const float* bP = Bw + (size_t)(n0 + bn) * K + bkq;

    float acc[8][4];
    #pragma unroll
    for (int i = 0; i < 8; i++)
        #pragma unroll
        for (int j = 0; j < 4; j++) acc[i][j] = 0.f;

    float4 ar0 = *(const float4*)(aP);
    float4 ar1 = *(const float4*)(aP + 4);
    float4 br0 = *(const float4*)(bP);

    int buf = 0;
    {
        float* As = u.s.As[0]; float* Bs = u.s.Bs[0];
        As[(akq+0)*AS_STRIDE+am]=ar0.x; As[(akq+1)*AS_STRIDE+am]=ar0.y;
        As[(akq+2)*AS_STRIDE+am]=ar0.z; As[(akq+3)*AS_STRIDE+am]=ar0.w;
        As[(akq+4)*AS_STRIDE+am]=ar1.x; As[(akq+5)*AS_STRIDE+am]=ar1.y;
        As[(akq+6)*AS_STRIDE+am]=ar1.z; As[(akq+7)*AS_STRIDE+am]=ar1.w;
        Bs[(bkq+0)*BS_STRIDE+bn]=br0.x; Bs[(bkq+1)*BS_STRIDE+bn]=br0.y;
        Bs[(bkq+2)*BS_STRIDE+bn]=br0.z; Bs[(bkq+3)*BS_STRIDE+bn]=br0.w;
    }
    __syncthreads();

    int nch = K / 16;
    for (int c = 0; c < nch; c++) {
        if (c + 1 < nch) {
            ar0 = *(const float4*)(aP + (c+1)*16);
            ar1 = *(const float4*)(aP + (c+1)*16 + 4);
            br0 = *(const float4*)(bP + (c+1)*16);
        }
        const float* As = u.s.As[buf];
        const float* Bs = u.s.Bs[buf];
        #pragma unroll
        for (int kk = 0; kk < 16; kk++) {
            float4 a0 = *(const float4*)&As[kk*AS_STRIDE + ty*8];
            float4 a1 = *(const float4*)&As[kk*AS_STRIDE + ty*8 + 4];
            float4 b0 = *(const float4*)&Bs[kk*BS_STRIDE + tx*4];
            float ar[8] = {a0.x,a0.y,a0.z,a0.w,a1.x,a1.y,a1.z,a1.w};
            float br[4] = {b0.x,b0.y,b0.z,b0.w};
            #pragma unroll
            for (int i = 0; i < 8; i++)
                #pragma unroll
                for (int j = 0; j < 4; j++)
                    acc[i][j] = fmaf(ar[i], br[j], acc[i][j]);
        }
        if (c + 1 < nch) {
            __syncthreads();
            float* Asw = u.s.As[buf^1]; float* Bsw = u.s.Bs[buf^1];
            Asw[(akq+0)*AS_STRIDE+am]=ar0.x; Asw[(akq+1)*AS_STRIDE+am]=ar0.y;
            Asw[(akq+2)*AS_STRIDE+am]=ar0.z; Asw[(akq+3)*AS_STRIDE+am]=ar0.w;
            Asw[(akq+4)*AS_STRIDE+am]=ar1.x; Asw[(akq+5)*AS_STRIDE+am]=ar1.y;
            Asw[(akq+6)*AS_STRIDE+am]=ar1.z; Asw[(akq+7)*AS_STRIDE+am]=ar1.w;
            Bsw[(bkq+0)*BS_STRIDE+bn]=br0.x; Bsw[(bkq+1)*BS_STRIDE+bn]=br0.y;
            Bsw[(bkq+2)*BS_STRIDE+bn]=br0.z; Bsw[(bkq+3)*BS_STRIDE+bn]=br0.w;
            __syncthreads();
            buf ^= 1;
        }
    }

    bool transp = (MODE == 0 && n0 < DI) || (MODE == 1);
    if (transp) {
        __syncthreads();
        #pragma unroll
        for (int i = 0; i < 8; i++)
            #pragma unroll
            for (int j = 0; j < 4; j++)
                u.Ts[(tx*4+j)*129 + ty*8+i] = acc[i][j];
        __syncthreads();
        int b = m0 >> 12, l0 = m0 & 4095;
        float* dst = (MODE == 0) ? g_xa_pre : g_c_pre;
        for (int e = tid; e < 64*128; e += 256) {
            int row = e >> 7, cc = e & 127;
            dst[((size_t)(b*DI + n0 + row))*LL + l0 + cc] = u.Ts[row*129 + cc];
        }
    } else {
        #pragma unroll
        for (int i = 0; i < 8; i++) {
            int m = m0 + ty*8 + i;
            #pragma unroll
            for (int j = 0; j < 4; j++) {
                int n = n0 + tx*4 + j;
                float v = acc[i][j];
                if (MODE == 0)      g_z[(size_t)m*DI + (n - DI)] = silu_f(v);
                else if (MODE == 2) out[(size_t)m*N + n] = v;
            }
        }
    }
}

// =======================================================================
// depthwise conv 3x3 SAME + bias + silu, one (tensor,b,d) image per block
// =======================================================================
__global__ void __launch_bounds__(256) dwconv_k(const float* __restrict__ conv_w,
        const float* __restrict__ conv_b, const float* __restrict__ con_w,
        const float* __restrict__ con_b)
{
    __shared__ __align__(16) float img[LL];
    int blk = blockIdx.x;
    int t  = blk >= BB*DI;
    int bd = t ? blk - BB*DI : blk;
    int d  = bd % DI;
    const float* in  = (t ? g_c_pre : g_xa_pre) + (size_t)bd * LL;
    float*       oup = (t ? g_c_conv : g_xa_conv) + (size_t)bd * LL;
    const float* wp  = (t ? con_w : conv_w) + d * 9;
    float bias = (t ? con_b : conv_b)[d];

    #pragma unroll
    for (int i = 0; i < 4; i++)
        *(float4*)&img[(threadIdx.x + 256*i)*4] = *(const float4*)&in[(threadIdx.x + 256*i)*4];
    float w0=wp[0],w1=wp[1],w2=wp[2],w3=wp[3],w4=wp[4],w5=wp[5],w6=wp[6],w7=wp[7],w8=wp[8];
    __syncthreads();

    #pragma unroll
    for (int i = 0; i < 16; i++) {
        int l = threadIdx.x + 256*i;
        int y = l >> 6, x = l & 63;
        float acc = bias;
        bool yl = y > 0, yh = y < 63, xl = x > 0, xh = x < 63;
        if (yl) {
            if (xl) acc = fmaf(img[l-65], w0, acc);
            acc = fmaf(img[l-64], w1, acc);
            if (xh) acc = fmaf(img[l-63], w2, acc);
        }
        if (xl) acc = fmaf(img[l-1], w3, acc);
        acc = fmaf(img[l], w4, acc);
        if (xh) acc = fmaf(img[l+1], w5, acc);
        if (yh) {
            if (xl) acc = fmaf(img[l+63], w6, acc);
            acc = fmaf(img[l+64], w7, acc);
            if (xh) acc = fmaf(img[l+65], w8, acc);
        }
        oup[l] = silu_f(acc);
    }
}

// =======================================================================
// proj v2: block = 64 pixels (one image row), 256 thr.
// Stage 1: register-blocked GEMM [64x48] = [64x384]x[384x48] (x_proj).
// Stage 2: dt_proj + softplus + scatter (delta,u) / (B,C) to scan order.
// =======================================================================
__global__ void __launch_bounds__(256) proj_k(const float* __restrict__ x_proj_w,
        const float* __restrict__ dt_proj_w, const float* __restrict__ dt_proj_b,
        const int* __restrict__ rev_scan)
{
    __shared__ float sDT[DI*13];      // dt_proj_w padded rows (conflict-free)
    __shared__ float sDTB[DI];
    __shared__ float xd[64*49];       // x_dbl per pixel (48 outputs, pad 49)
    __shared__ __align__(16) union {
        struct { float sS[16*68]; float sB[16*48]; } a;
        float xaT[32*69];
    } u;

    int tid = threadIdx.x;
    int b   = blockIdx.x >> 6;
    int l0  = (blockIdx.x & 63) * 64;

    // stage dt tables
    for (int e = tid; e < DI*DR; e += 256)
        sDT[(e/DR)*13 + (e%DR)] = dt_proj_w[e];
    if (tid < 128) {
        sDTB[tid]       = dt_proj_b[tid];
        sDTB[tid+128]   = dt_proj_b[tid+128];
        sDTB[tid+256]   = dt_proj_b[tid+256];
    }

    int tm = tid & 15, tn = tid >> 4;
    float acc[4][3];
    #pragma unroll
    for (int i = 0; i < 4; i++)
        #pragma unroll
        for (int j = 0; j < 3; j++) acc[i][j] = 0.f;

    // ---- stage 1: x_proj GEMM over K=384 in chunks of 16 ----
    for (int kc = 0; kc < DI/16; kc++) {
        __syncthreads();
        #pragma unroll
        for (int i = 0; i < 4; i++) {
            int e = tid + 256*i;
            int k = e >> 6, px = e & 63;
            size_t off = ((size_t)(b*DI + kc*16 + k))*LL + l0 + px;
            u.a.sS[k*68 + px] = g_xa_conv[off] + g_c_conv[off];
        }
        #pragma unroll
        for (int i = 0; i < 3; i++) {
            int e = tid + 256*i;
            int cc = e >> 4, kk = e & 15;
            u.a.sB[kk*48 + cc] = (cc < DR + 2*DS)
                ? __ldg(&x_proj_w[(size_t)cc*DI + kc*16 + kk]) : 0.f;
        }
        __syncthreads();
        #pragma unroll
        for (int k = 0; k < 16; k++) {
            float4 av = *(const float4*)&u.a.sS[k*68 + tm*4];
            float b0 = u.a.sB[k*48 + tn*3 + 0];
            float b1 = u.a.sB[k*48 + tn*3 + 1];
            float b2 = u.a.sB[k*48 + tn*3 + 2];
            float ar[4] = {av.x, av.y, av.z, av.w};
            #pragma unroll
            for (int i = 0; i < 4; i++) {
                acc[i][0] = fmaf(ar[i], b0, acc[i][0]);
                acc[i][1] = fmaf(ar[i], b1, acc[i][1]);
                acc[i][2] = fmaf(ar[i], b2, acc[i][2]);
            }
        }
    }
    #pragma unroll
    for (int i = 0; i < 4; i++)
        #pragma unroll
        for (int j = 0; j < 3; j++)
            xd[(tm*4+i)*49 + tn*3+j] = acc[i][j];
    __syncthreads();

    int w = tid >> 5, lane = tid & 31;

    // ---- B/C scatter ----
    #pragma unroll
    for (int p = 0; p < 4; p++) {
        int px = w*8 + p*2 + (lane >> 4);
        int n  = lane & 15;
        int j  = __ldg(&rev_scan[l0 + px]);
        g_bc[((size_t)b*LL + j)*DS + n] =
            make_float2(xd[px*49 + DR + n], xd[px*49 + DR + DS + n]);
    }

    // ---- stage 2: delta + u scatter, 32-d chunks ----
    for (int c32 = 0; c32 < DI/32; c32++) {
        __syncthreads();
        #pragma unroll
        for (int i = 0; i < 8; i++) {
            int e = tid + 256*i;
            int dd = e >> 6, px = e & 63;
            u.xaT[dd*69 + px] =
                g_xa_conv[((size_t)(b*DI + c32*32 + dd))*LL + l0 + px];
        }
        __syncthreads();
        int d = c32*32 + lane;
        float wr[DR];
        #pragma unroll
        for (int r = 0; r < DR; r++) wr[r] = sDT[d*13 + r];
        float bias = sDTB[d];
        #pragma unroll
        for (int p = 0; p < 8; p++) {
            int px = p*8 + w;
            float a = bias;
            #pragma unroll
            for (int r = 0; r < DR; r++) a = fmaf(wr[r], xd[px*49 + r], a);
            float delta = (a > 20.f) ? a : log1pf(__expf(a));
            float uval  = u.xaT[lane*69 + px];
            int j = __ldg(&rev_scan[l0 + px]);
            g_du[((size_t)b*LL + j)*DI + d] = make_float2(delta, uval);
        }
    }
}

// =======================================================================
// selective scan: block = 8 channels of one batch, 128 thr
// =======================================================================
#define TSTEP 32
#define NTILE (LL/TSTEP)   // 128

__global__ void __launch_bounds__(128) scan_k(const float* __restrict__ A_logs,
        const float* __restrict__ Ds, const int* __restrict__ scan_path)
{
    __shared__ __align__(16) float2 du2[2][TSTEP][8];
    __shared__ __align__(16) float2 bc2[2][TSTEP][DS];
    __shared__ float  ps[TSTEP*8*17];
    __shared__ float  s_D[8];

    int tid = threadIdx.x;
    int b   = blockIdx.x / 48;
    int d0  = (blockIdx.x % 48) * 8;
    int wid = tid >> 5, lane = tid & 31;
    int g = lane >> 4, n = lane & 15;
    int ch = wid*2 + g;
    int d = d0 + ch;

    float a_coef = -__expf(A_logs[d*DS + n]);
    if (tid < 8) s_D[tid] = Ds[d0 + tid];

    unsigned du_sm = (unsigned)__cvta_generic_to_shared(&du2[0][0][0]);
    unsigned bc_sm = (unsigned)__cvta_generic_to_shared(&bc2[0][0][0]);
    const float2* du_g = g_du + (size_t)b*LL*DI + d0;
    const float2* bc_g = g_bc + (size_t)b*LL*DS;

    {
        #pragma unroll
        for (int i = 0; i < 2; i++) {
            int e = tid + 128*i;
            int jj = e >> 3, c = e & 7;
            cpa8(du_sm + (unsigned)((jj*8 + c)*8), du_g + (size_t)jj*DI + c);
        }
        #pragma unroll
        for (int i = 0; i < 2; i++) {
            int e = tid + 128*i;
            int jj = e >> 3, q = e & 7;
            cpa16(bc_sm + (unsigned)((jj*DS + q*2)*8), bc_g + (size_t)jj*DS + q*2);
        }
        cp_commit();
    }

    float h = 0.f;
    int buf = 0;
    for (int T = 0; T < NTILE; T++) {
        if (T + 1 < NTILE) {
            int o = (buf^1) * TSTEP;
            #pragma unroll
            for (int i = 0; i < 2; i++) {
                int e = tid + 128*i;
                int jj = e >> 3, c = e & 7;
                cpa8(du_sm + (unsigned)(((o+jj)*8 + c)*8),
                     du_g + (size_t)((T+1)*TSTEP + jj)*DI + c);
            }
            #pragma unroll
            for (int i = 0; i < 2; i++) {
                int e = tid + 128*i;
                int jj = e >> 3, q = e & 7;
                cpa16(bc_sm + (unsigned)(((o+jj)*DS + q*2)*8),
                      bc_g + (size_t)((T+1)*TSTEP + jj)*DS + q*2);
            }
            cp_commit();
            cp_wait1();
        } else {
            cp_wait0();
        }
        __syncthreads();

        #pragma unroll 8
        for (int jj = 0; jj < TSTEP; jj++) {
            float2 du = du2[buf][jj][ch];
            float2 bc = bc2[buf][jj][n];
            float dA = __expf(du.x * a_coef);
            h = fmaf(dA, h, du.x * du.y * bc.x);
            ps[(jj*8 + ch)*17 + n] = h * bc.y;
        }
        __syncthreads();

        #pragma unroll
        for (int i = 0; i < 2; i++) {
            int e = tid + 128*i;
            int jj = e >> 3, c = e & 7;
            const float* p = &ps[(jj*8 + c)*17];
            float sum = p[0];
            #pragma unroll
            for (int k = 1; k < DS; k++) sum += p[k];
            float uval = du2[buf][jj][c].y;
            int pos = __ldg(&scan_path[T*TSTEP + jj]);
            g_y[((size_t)b*LL + pos)*DI + d0 + c] = fmaf(uval, s_D[c], sum);
        }
        buf ^= 1;
    }
}

// =======================================================================
// layernorm over d + multiply by silu(z)
// =======================================================================
__global__ void __launch_bounds__(128) ln_mul_k(const float* __restrict__ ln_w,
                                                const float* __restrict__ ln_b)
{
    int row = blockIdx.x;
    const float* yr = g_y + (size_t)row * DI;
    float v0 = yr[threadIdx.x], v1 = yr[threadIdx.x + 128], v2 = yr[threadIdx.x + 256];
    float s = v0 + v1 + v2;
    float q = v0*v0 + v1*v1 + v2*v2;
    #pragma unroll
    for (int o = 16; o > 0; o >>= 1) {
        s += __shfl_xor_sync(0xFFFFFFFFu, s, o);
        q += __shfl_xor_sync(0xFFFFFFFFu, q, o);
    }
    __shared__ float ss[4], sq[4];
    int w = threadIdx.x >> 5, lane = threadIdx.x & 31;
    if (lane == 0) { ss[w] = s; sq[w] = q; }
    __syncthreads();
    s = ss[0] + ss[1] + ss[2] + ss[3];
    q = sq[0] + sq[1] + sq[2] + sq[3];
    float mean = s * (1.f / DI);
    float var  = q * (1.f / DI) - mean * mean;
    float rstd = rsqrtf(var + 1e-5f);
    const float* zr = g_z + (size_t)row * DI;
    float* o = g_yz + (size_t)row * DI;
    float vv[3] = {v0, v1, v2};
    #pragma unroll
    for (int i = 0; i < 3; i++) {
        int dd = threadIdx.x + i * 128;
        o[dd] = ((vv[i] - mean) * rstd * ln_w[dd] + ln_b[dd]) * zr[dd];
    }
}

// ---------------- launch ----------------
extern "C" void kernel_launch(void* const* d_in, const int* in_sizes, int n_in,
                              void* d_out, int out_size)
{
    const float* x          = (const float*)d_in[0];
    const float* cond       = (const float*)d_in[1];
    const float* W_in       = (const float*)d_in[2];
    const float* W_con      = (const float*)d_in[3];
    const float* conv_w     = (const float*)d_in[4];
    const float* conv_b     = (const float*)d_in[5];
    const float* con_conv_w = (const float*)d_in[6];
    const float* con_conv_b = (const float*)d_in[7];
    const float* x_proj_w   = (const float*)d_in[8];
    const float* dt_proj_w  = (const float*)d_in[9];
    const float* dt_proj_b  = (const float*)d_in[10];
    const float* A_logs     = (const float*)d_in[11];
    const float* Ds         = (const float*)d_in[12];
    const float* ln_w       = (const float*)d_in[13];
    const float* ln_b       = (const float*)d_in[14];
    const float* W_out      = (const float*)d_in[15];
    const int*   scan_path  = (const int*)d_in[16];
    const int*   rev_scan   = (const int*)d_in[17];
    float* out = (float*)d_out;

    gemm_k<0><<<dim3(2*DI/64, NROWS/128), 256>>>(x,    W_in,  NROWS, 2*DI, DM, nullptr);
    gemm_k<1><<<dim3(DI/64,   NROWS/128), 256>>>(cond, W_con, NROWS, DI,   DM, nullptr);
    dwconv_k<<<2*BB*DI, 256>>>(conv_w, conv_b, con_conv_w, con_conv_b);
    proj_k<<<NROWS/64, 256>>>(x_proj_w, dt_proj_w, dt_proj_b, rev_scan);
    scan_k<<<(BB*DI)/8, 128>>>(A_logs, Ds, scan_path);
    ln_mul_k<<<NROWS, 128>>>(ln_w, ln_b);
    gemm_k<2><<<dim3(DM/64, NROWS/128), 256>>>(nullptr, W_out, NROWS, DM, DI, out);
}